// round 3
// baseline (speedup 1.0000x reference)
#include <cuda_runtime.h>

// out[b,e,t] = v2[t]*x[b,e,t] + bias[t] + P[t]
// P[t] = sum_{s<t} x[b,e,s]*w[s]*d^(t-s),  d = clip(decay[1], 0.9, 1.0)
//
// Decayed prefix scan along S. All scan multipliers are data-independent
// powers of d, so only the additive term is shuffled. Two rows are processed
// per iteration to (a) interleave two independent shuffle/FMA chains,
// (b) double the x-prefetch distance, (c) halve barrier count.

#define SEQ 2048
#define CHUNK 8
#define THREADS 256          // 256 * 8 = 2048 = SEQ
#define RPB 8                // rows per block

__global__ void __launch_bounds__(THREADS)
decay_scan_kernel(const float* __restrict__ x,
                  const float* __restrict__ w,
                  const float* __restrict__ v2,
                  const float* __restrict__ bias,
                  const float* __restrict__ decay,
                  float* __restrict__ out,
                  int rows)
{
    const int tid   = threadIdx.x;
    const int lane  = tid & 31;
    const int warp  = tid >> 5;
    const int sbase = tid * CHUNK;

    const float d = fminf(fmaxf(decay[1], 0.9f), 1.0f);

    // decay powers (uniform, data-independent)
    float d8 = d * d; d8 = d8 * d8; d8 = d8 * d8;   // d^8
    const float m1 = d8;
    const float m2 = m1 * m1;
    const float m4 = m2 * m2;
    const float m8 = m4 * m4;
    const float m16 = m8 * m8;
    const float d256 = m16 * m16;
    const float Me = exp2f(8.0f * (float)lane * __log2f(d));  // d^(8*lane)

    // register-cached params for this thread's chunk
    float4 w0  = *reinterpret_cast<const float4*>(w    + sbase);
    float4 w1  = *reinterpret_cast<const float4*>(w    + sbase + 4);
    float4 v20 = *reinterpret_cast<const float4*>(v2   + sbase);
    float4 v21 = *reinterpret_cast<const float4*>(v2   + sbase + 4);
    float4 b0  = *reinterpret_cast<const float4*>(bias + sbase);
    float4 b1  = *reinterpret_cast<const float4*>(bias + sbase + 4);
    float wv[CHUNK] = {w0.x, w0.y, w0.z, w0.w, w1.x, w1.y, w1.z, w1.w};
    float vv[CHUNK] = {v20.x, v20.y, v20.z, v20.w, v21.x, v21.y, v21.z, v21.w};
    float bv[CHUNK] = {b0.x, b0.y, b0.z, b0.w, b1.x, b1.y, b1.z, b1.w};

    __shared__ float sA[2][2][THREADS / 32];  // [parity][row-in-pair][warp]

    const int row0 = blockIdx.x * RPB;

    // prefetch pair 0
    float4 pa0 = make_float4(0,0,0,0), pa1 = pa0, pb0 = pa0, pb1 = pa0;
    {
        const float* xp = x + (long long)row0 * SEQ + sbase;
        if (row0 < rows)     { pa0 = *reinterpret_cast<const float4*>(xp);
                               pa1 = *reinterpret_cast<const float4*>(xp + 4); }
        if (row0 + 1 < rows) { pb0 = *reinterpret_cast<const float4*>(xp + SEQ);
                               pb1 = *reinterpret_cast<const float4*>(xp + SEQ + 4); }
    }

#pragma unroll 1
    for (int r = 0; r < RPB; r += 2) {
        const int rowA = row0 + r;
        const int rowB = rowA + 1;

        // prefetch next pair (a full 2-row iteration ahead)
        float4 na0, na1, nb0, nb1;
        if (r + 2 < RPB) {
            const float* xn = x + (long long)(rowA + 2) * SEQ + sbase;
            if (rowA + 2 < rows) { na0 = *reinterpret_cast<const float4*>(xn);
                                   na1 = *reinterpret_cast<const float4*>(xn + 4); }
            if (rowB + 2 < rows) { nb0 = *reinterpret_cast<const float4*>(xn + SEQ);
                                   nb1 = *reinterpret_cast<const float4*>(xn + SEQ + 4); }
        }

        float xA[CHUNK] = {pa0.x, pa0.y, pa0.z, pa0.w, pa1.x, pa1.y, pa1.z, pa1.w};
        float xB[CHUNK] = {pb0.x, pb0.y, pb0.z, pb0.w, pb1.x, pb1.y, pb1.z, pb1.w};

        // per-chunk additive terms (two independent chains)
        float Aa = 0.f, Ab = 0.f;
#pragma unroll
        for (int j = 0; j < CHUNK; j++) {
            Aa = d * fmaf(xA[j], wv[j], Aa);
            Ab = d * fmaf(xB[j], wv[j], Ab);
        }

        // interleaved Kogge-Stone scans (independent chains hide SHFL latency)
        float Sa = Aa, Sb = Ab;
        {
            float ta, tb;
            ta = __shfl_up_sync(0xffffffffu, Sa, 1);
            tb = __shfl_up_sync(0xffffffffu, Sb, 1);
            if (lane >= 1)  { Sa = fmaf(m1,  ta, Sa); Sb = fmaf(m1,  tb, Sb); }
            ta = __shfl_up_sync(0xffffffffu, Sa, 2);
            tb = __shfl_up_sync(0xffffffffu, Sb, 2);
            if (lane >= 2)  { Sa = fmaf(m2,  ta, Sa); Sb = fmaf(m2,  tb, Sb); }
            ta = __shfl_up_sync(0xffffffffu, Sa, 4);
            tb = __shfl_up_sync(0xffffffffu, Sb, 4);
            if (lane >= 4)  { Sa = fmaf(m4,  ta, Sa); Sb = fmaf(m4,  tb, Sb); }
            ta = __shfl_up_sync(0xffffffffu, Sa, 8);
            tb = __shfl_up_sync(0xffffffffu, Sb, 8);
            if (lane >= 8)  { Sa = fmaf(m8,  ta, Sa); Sb = fmaf(m8,  tb, Sb); }
            ta = __shfl_up_sync(0xffffffffu, Sa, 16);
            tb = __shfl_up_sync(0xffffffffu, Sb, 16);
            if (lane >= 16) { Sa = fmaf(m16, ta, Sa); Sb = fmaf(m16, tb, Sb); }
        }

        const int p = (r >> 1) & 1;
        if (lane == 31) { sA[p][0][warp] = Sa; sA[p][1][warp] = Sb; }
        __syncthreads();

        // cross-warp carries (uniform multiplier d^256)
        float Ca = 0.f, Cb = 0.f;
#pragma unroll
        for (int wi = 0; wi < THREADS / 32; wi++) {
            if (wi < warp) {
                Ca = fmaf(d256, Ca, sA[p][0][wi]);
                Cb = fmaf(d256, Cb, sA[p][1][wi]);
            }
        }

        float Ea = __shfl_up_sync(0xffffffffu, Sa, 1);
        float Eb = __shfl_up_sync(0xffffffffu, Sb, 1);
        if (lane == 0) { Ea = 0.f; Eb = 0.f; }

        float PA = fmaf(Me, Ca, Ea);
        float PB = fmaf(Me, Cb, Eb);

        // epilogues
        float oA[CHUNK], oB[CHUNK];
#pragma unroll
        for (int j = 0; j < CHUNK; j++) {
            oA[j] = fmaf(vv[j], xA[j], PA + bv[j]);
            PA = d * fmaf(xA[j], wv[j], PA);
            oB[j] = fmaf(vv[j], xB[j], PB + bv[j]);
            PB = d * fmaf(xB[j], wv[j], PB);
        }

        float* opA = out + (long long)rowA * SEQ + sbase;
        if (rowA < rows) {
            *reinterpret_cast<float4*>(opA)     = make_float4(oA[0], oA[1], oA[2], oA[3]);
            *reinterpret_cast<float4*>(opA + 4) = make_float4(oA[4], oA[5], oA[6], oA[7]);
        }
        if (rowB < rows) {
            *reinterpret_cast<float4*>(opA + SEQ)     = make_float4(oB[0], oB[1], oB[2], oB[3]);
            *reinterpret_cast<float4*>(opA + SEQ + 4) = make_float4(oB[4], oB[5], oB[6], oB[7]);
        }

        pa0 = na0; pa1 = na1; pb0 = nb0; pb1 = nb1;
    }
}

extern "C" void kernel_launch(void* const* d_in, const int* in_sizes, int n_in,
                              void* d_out, int out_size)
{
    const float* x     = (const float*)d_in[0];  // (B, E, S)
    const float* w     = (const float*)d_in[1];  // (1, S)
    const float* v2    = (const float*)d_in[2];  // (1, S)
    const float* bias  = (const float*)d_in[3];  // (S,)
    const float* decay = (const float*)d_in[4];  // (2, 1)
    float* out = (float*)d_out;

    const int rows   = in_sizes[0] / SEQ;        // B * E
    const int blocks = (rows + RPB - 1) / RPB;
    decay_scan_kernel<<<blocks, THREADS>>>(x, w, v2, bias, decay, out, rows);
}

// round 4
// speedup vs baseline: 1.0506x; 1.0506x over previous
#include <cuda_runtime.h>

// out[b,e,t] = v2[t]*x[b,e,t] + bias[t] + P[t]
// P[t] = sum_{s<t} x[b,e,s]*w[s]*d^(t-s),  d = clip(decay[1], 0.9, 1.0)
//
// Decayed prefix scan along S. All scan multipliers are data-independent
// powers of d, so only the additive term is shuffled. Small per-thread chunk
// (4 elems) keeps registers low -> high occupancy -> TLP hides latency.

#define SEQ 2048
#define CHUNK 4
#define THREADS 512          // 512 * 4 = 2048 = SEQ
#define NWARP (THREADS / 32)
#define RPB 8                // rows per block (params register-cached)

__global__ void __launch_bounds__(THREADS)
decay_scan_kernel(const float* __restrict__ x,
                  const float* __restrict__ w,
                  const float* __restrict__ v2,
                  const float* __restrict__ bias,
                  const float* __restrict__ decay,
                  float* __restrict__ out,
                  int rows)
{
    const int tid   = threadIdx.x;
    const int lane  = tid & 31;
    const int warp  = tid >> 5;
    const int sbase = tid * CHUNK;

    const float d = fminf(fmaxf(decay[1], 0.9f), 1.0f);

    // decay powers (uniform, data-independent)
    const float d2 = d * d;
    const float d4 = d2 * d2;          // per-chunk multiplier
    const float m1  = d4;              // scan step 1 : d^4
    const float m2  = m1 * m1;         //           2 : d^8
    const float m4  = m2 * m2;         //           4 : d^16
    const float m8  = m4 * m4;         //           8 : d^32
    const float m16 = m8 * m8;         //          16 : d^64
    const float d128 = m16 * m16;      // per-warp    : d^128
    const float Me = exp2f(4.0f * (float)lane * __log2f(d));  // d^(4*lane)

    // register-cached params for this thread's chunk
    const float4 wq = *reinterpret_cast<const float4*>(w    + sbase);
    const float4 vq = *reinterpret_cast<const float4*>(v2   + sbase);
    const float4 bq = *reinterpret_cast<const float4*>(bias + sbase);

    __shared__ float sA[2][NWARP];

    const int row0 = blockIdx.x * RPB;

    // prefetch first row
    float4 xa = make_float4(0.f, 0.f, 0.f, 0.f);
    if (row0 < rows)
        xa = *reinterpret_cast<const float4*>(x + (long long)row0 * SEQ + sbase);

#pragma unroll 1
    for (int r = 0; r < RPB; r++) {
        const int row = row0 + r;
        if (row >= rows) break;

        // prefetch next row
        float4 xb;
        if (r + 1 < RPB && row + 1 < rows)
            xb = *reinterpret_cast<const float4*>(x + (long long)(row + 1) * SEQ + sbase);

        // per-chunk additive term: A = sum_j x[j]*w[j]*d^(CHUNK-j)
        float A;
        A = d * (xa.x * wq.x);
        A = d * fmaf(xa.y, wq.y, A);
        A = d * fmaf(xa.z, wq.z, A);
        A = d * fmaf(xa.w, wq.w, A);

        // Kogge-Stone scan of A (multipliers are precomputed powers of d)
        float Ai = A;
        {
            float ap;
            ap = __shfl_up_sync(0xffffffffu, Ai, 1);  if (lane >= 1)  Ai = fmaf(m1,  ap, Ai);
            ap = __shfl_up_sync(0xffffffffu, Ai, 2);  if (lane >= 2)  Ai = fmaf(m2,  ap, Ai);
            ap = __shfl_up_sync(0xffffffffu, Ai, 4);  if (lane >= 4)  Ai = fmaf(m4,  ap, Ai);
            ap = __shfl_up_sync(0xffffffffu, Ai, 8);  if (lane >= 8)  Ai = fmaf(m8,  ap, Ai);
            ap = __shfl_up_sync(0xffffffffu, Ai, 16); if (lane >= 16) Ai = fmaf(m16, ap, Ai);
        }

        const int p = r & 1;
        if (lane == 31) sA[p][warp] = Ai;
        __syncthreads();

        // cross-warp carry (uniform multiplier d^128)
        float Cw = 0.f;
#pragma unroll
        for (int wi = 0; wi < NWARP; wi++)
            if (wi < warp) Cw = fmaf(d128, Cw, sA[p][wi]);

        // exclusive additive within warp
        float Ae = __shfl_up_sync(0xffffffffu, Ai, 1);
        if (lane == 0) Ae = 0.f;

        float C = fmaf(Me, Cw, Ae);     // P at start of this thread's chunk

        // epilogue: out[t] = v2[t]*x[t] + bias[t] + P[t]
        float4 o;
        o.x = fmaf(vq.x, xa.x, C + bq.x);  C = d * fmaf(xa.x, wq.x, C);
        o.y = fmaf(vq.y, xa.y, C + bq.y);  C = d * fmaf(xa.y, wq.y, C);
        o.z = fmaf(vq.z, xa.z, C + bq.z);  C = d * fmaf(xa.z, wq.z, C);
        o.w = fmaf(vq.w, xa.w, C + bq.w);

        *reinterpret_cast<float4*>(out + (long long)row * SEQ + sbase) = o;

        xa = xb;
    }
}

extern "C" void kernel_launch(void* const* d_in, const int* in_sizes, int n_in,
                              void* d_out, int out_size)
{
    const float* x     = (const float*)d_in[0];  // (B, E, S)
    const float* w     = (const float*)d_in[1];  // (1, S)
    const float* v2    = (const float*)d_in[2];  // (1, S)
    const float* bias  = (const float*)d_in[3];  // (S,)
    const float* decay = (const float*)d_in[4];  // (2, 1)
    float* out = (float*)d_out;

    const int rows   = in_sizes[0] / SEQ;        // B * E
    const int blocks = (rows + RPB - 1) / RPB;
    decay_scan_kernel<<<blocks, THREADS>>>(x, w, v2, bias, decay, out, rows);
}